// round 12
// baseline (speedup 1.0000x reference)
#include <cuda_runtime.h>
#include <cuda_bf16.h>
#include <math.h>
#include <float.h>
#include <cstdint>

#define NPTS   32768
#define NE     1024
#define ED     64
#define ZELEMS 2097152

// Output layout: [loss(1), z_q_st(2097152), perplexity(1), min_encodings(33554432), idx(32768)]
#define OFF_LOSS 0
#define OFF_ZQ   1
#define OFF_PERP 2097153
#define OFF_MENC 2097154
#define OFF_IDX  35651586

__device__ float    g_see[NE];
__device__ float    g_szz[NPTS];
__device__ int      g_idx[NPTS];
__device__ int      g_cs[NE];
__device__ float    g_sum[NE * ED];
__device__ float    g_new_emb[NE * ED];
__device__ float    g_loss_sum;
__device__ unsigned g_ticket;

__device__ __forceinline__ uint32_t smem_u32(const void* p) {
    uint32_t a;
    asm("{ .reg .u64 t; cvta.to.shared.u64 t, %1; cvt.u32.u64 %0, t; }" : "=r"(a) : "l"(p));
    return a;
}

// ---------------------------------------------------------------------------
// K1: per-code ||e||^2, per-point ||z||^2, zero accumulators (R7 prep).
// ---------------------------------------------------------------------------
__global__ void k_prep(const float* __restrict__ z, const float* __restrict__ emb)
{
    int t = blockIdx.x * 256 + threadIdx.x;   // 32768 threads
    if (t < NE) {
        const float* e = emb + (size_t)t * ED;
        float s = 0.f;
        #pragma unroll
        for (int c = 0; c < ED; c++) { float v = e[c]; s = __fadd_rn(s, __fmul_rn(v, v)); }
        g_see[t] = s;
        g_cs[t]  = 0;
    }
    if (t == 0) { g_loss_sum = 0.f; g_ticket = 0u; }
    if (t < NPTS) {
        int b = t >> 10, hw = t & 1023;
        const float* zp = z + (size_t)b * 65536 + hw;
        float s = 0.f;
        #pragma unroll
        for (int c = 0; c < ED; c++) { float v = zp[(size_t)c << 10]; s = __fadd_rn(s, __fmul_rn(v, v)); }
        g_szz[t] = s;
    }
    g_sum[t]          = 0.f;
    g_sum[t + 32768]  = 0.f;
}

// ---------------------------------------------------------------------------
// K2: two-round bf16 mma.sync screen + batched exact fp32 rescreen + fused
// cluster stats (R7 structure, 143.8us proven), with per-lane hoisted B
// addresses (SWB is affine in nt for fixed lane) and float2 see loads.
//
// Round 1: HMMA GEMM over all 1024 codes; epilogue = running min of
//   dt_j = see_j - 2*(z_bf16 . e_bf16)  (4 fminf per n-tile, nothing else).
// Round 2: identical deterministic GEMM; push j with dt_j < min + MARGIN
//   into a per-point smem list (expected 1-3 entries; cap 16 + full-scan
//   fallback on overflow).
// Exact phase: candidates re-evaluated with the EXACT fp32 expression of
//   rounds 1-3 (same fmaf chain, k ascending); u64 (d_bits<<32|j) atomicMin
//   = exact first-index tie-break -> argmin bit-identical to the FFMA kernel.
//   Screen error bound ~1.3e-4 << MARGIN 2e-3 guarantees containment.
//
// Dyn smem: zA bf16 sw 16K | ES bf16 sw 16K | zs32 32K | see 512B |
//           lst u16 4K | cnt 512B | best 1K  = 71680 B -> 2 CTA/SM
// ---------------------------------------------------------------------------
#define SM_ZA    0
#define SM_ES    16384
#define SM_Z32   32768
#define SM_SEE   65536
#define SM_LST   66048
#define SM_CNT   70144
#define SM_BEST  70656
#define SM_TOT   71680

// XOR-swizzled byte offset for [row][k] bf16 tiles, 128B rows, 16B granules
#define SWB(row, kcol) ((uint32_t)(row) * 128u + (uint32_t)(((((kcol) >> 3) ^ ((row) & 7)) << 4) | (((kcol) & 7) << 1)))

__device__ __forceinline__ void exact_eval(int p, int j, const float (*zs32)[128],
                                           const float* __restrict__ emb, float szz,
                                           unsigned long long* bestp)
{
    const float4* ep = (const float4*)(emb + (size_t)j * ED);
    float acc = 0.f;
    #pragma unroll
    for (int k4 = 0; k4 < 16; k4++) {
        float4 e4 = __ldg(ep + k4);
        acc = fmaf(zs32[k4 * 4 + 0][p], e4.x, acc);
        acc = fmaf(zs32[k4 * 4 + 1][p], e4.y, acc);
        acc = fmaf(zs32[k4 * 4 + 2][p], e4.z, acc);
        acc = fmaf(zs32[k4 * 4 + 3][p], e4.w, acc);
    }
    float d = __fsub_rn(__fadd_rn(szz, g_see[j]), __fmul_rn(2.0f, acc));
    unsigned long long key = ((unsigned long long)__float_as_uint(d) << 32) | (unsigned)j;
    atomicMin(bestp, key);
}

__global__ __launch_bounds__(256, 2) void k_argmin_mma(const float* __restrict__ z,
                                                       const float* __restrict__ emb,
                                                       float* __restrict__ out, int out_size)
{
    extern __shared__ char smem[];
    __shared__ int sbj[128];
    const uint32_t sb = smem_u32(smem);
    const int tid  = threadIdx.x;
    const int warp = tid >> 5;
    const int lane = tid & 31;
    const int g    = lane >> 2;       // C-fragment row group 0..7
    const int tig  = lane & 3;        // thread-in-group (column pair)
    const int pbase = blockIdx.x * 128;

    float (*zs32)[128]        = (float (*)[128])(smem + SM_Z32);
    float* see_s              = (float*)(smem + SM_SEE);
    unsigned short* lst       = (unsigned short*)(smem + SM_LST);
    int* cnt                  = (int*)(smem + SM_CNT);
    unsigned long long* bestq = (unsigned long long*)(smem + SM_BEST);

    // ---- load z tile: fp32 [k][p] + bf16 swizzled [p][k]; init cnt/best ----
    for (int i = tid; i < 64 * 128; i += 256) {
        int p = i & 127, k = i >> 7;
        int pn = pbase + p;
        int b = pn >> 10, hw = pn & 1023;
        float v = z[(size_t)b * 65536 + (size_t)k * 1024 + hw];
        zs32[k][p] = v;
        *(__nv_bfloat16*)(smem + SM_ZA + SWB(p, k)) = __float2bfloat16(v);
    }
    if (tid < 128) { cnt[tid] = 0; bestq[tid] = 0xFFFFFFFFFFFFFFFFull; }
    __syncthreads();

    // ---- preload A fragments: warp's 16 points x K=64 (4 k-steps) ----
    uint32_t afr[4][4];
    {
        int m = lane >> 3, r = lane & 7;
        int row = warp * 16 + (m & 1) * 8 + r;
        #pragma unroll
        for (int ks = 0; ks < 4; ks++) {
            int kc = (ks * 2 + (m >> 1)) * 8;
            uint32_t addr = sb + SM_ZA + SWB(row, kc);
            asm volatile("ldmatrix.sync.aligned.m8n8.x4.shared.b16 {%0,%1,%2,%3}, [%4];"
                : "=r"(afr[ks][0]), "=r"(afr[ks][1]), "=r"(afr[ks][2]), "=r"(afr[ks][3])
                : "r"(addr));
        }
    }

    const int p0 = warp * 16 + g;
    const int p1 = p0 + 8;
    const float szz0 = g_szz[pbase + p0];
    const float szz1 = g_szz[pbase + p1];
    const float MARGIN = 2e-3f;

    // ---- per-lane hoisted B addresses:
    // SWB(nt*8+br, (ks*2+bm)*8) = nt*1024 + br*128 + (((ks*2+bm)^br)<<4)
    const int blane = lane & 15;
    const int bm = blane >> 3, br = blane & 7;
    uint32_t baddr[4];
    #pragma unroll
    for (int ks = 0; ks < 4; ks++)
        baddr[ks] = sb + SM_ES + (uint32_t)(br * 128) + (uint32_t)((((ks * 2 + bm) ^ br) & 7) << 4);

    float run0 = FLT_MAX, run1 = FLT_MAX;
    float thr0 = 0.f, thr1 = 0.f;

    for (int round = 0; round < 2; round++) {
        for (int chunk = 0; chunk < 8; chunk++) {
            const int j0 = chunk * 128;
            __syncthreads();
            // load 128-code bf16 chunk (swizzled) + see
            for (int i = tid; i < 128 * 16; i += 256) {
                int r  = i >> 4;
                int k4 = (i & 15) << 2;
                float4 v = *(const float4*)(emb + (size_t)(j0 + r) * ED + k4);
                __nv_bfloat16 b4[4] = { __float2bfloat16(v.x), __float2bfloat16(v.y),
                                        __float2bfloat16(v.z), __float2bfloat16(v.w) };
                *(uint2*)(smem + SM_ES + SWB(r, k4)) = *(uint2*)b4;
            }
            if (tid < 128) see_s[tid] = g_see[j0 + tid];
            __syncthreads();

            #pragma unroll 2
            for (int nt = 0; nt < 16; nt++) {
                const uint32_t ntoff = (uint32_t)nt * 1024u;
                float acc0 = 0.f, acc1 = 0.f, acc2 = 0.f, acc3 = 0.f;
                #pragma unroll
                for (int ks = 0; ks < 4; ks++) {
                    uint32_t b0, b1;
                    asm volatile("ldmatrix.sync.aligned.m8n8.x2.shared.b16 {%0,%1}, [%2];"
                        : "=r"(b0), "=r"(b1) : "r"(baddr[ks] + ntoff));
                    asm volatile("mma.sync.aligned.m16n8k16.row.col.f32.bf16.bf16.f32 "
                        "{%0,%1,%2,%3}, {%4,%5,%6,%7}, {%8,%9}, {%0,%1,%2,%3};"
                        : "+f"(acc0), "+f"(acc1), "+f"(acc2), "+f"(acc3)
                        : "r"(afr[ks][0]), "r"(afr[ks][1]), "r"(afr[ks][2]), "r"(afr[ks][3]),
                          "r"(b0), "r"(b1));
                }
                int jl  = nt * 8 + tig * 2;
                float2 se = *(const float2*)&see_s[jl];
                float dt0 = fmaf(acc0, -2.0f, se.x);
                float dt1 = fmaf(acc1, -2.0f, se.y);
                float dt2 = fmaf(acc2, -2.0f, se.x);
                float dt3 = fmaf(acc3, -2.0f, se.y);
                if (round == 0) {
                    run0 = fminf(run0, fminf(dt0, dt1));
                    run1 = fminf(run1, fminf(dt2, dt3));
                } else {
                    // push rare candidates (expected ~1-3 per point TOTAL)
                    if (dt0 < thr0) { int c = atomicAdd(&cnt[p0], 1); if (c < 16) lst[p0 * 16 + c] = (unsigned short)(j0 + jl); }
                    if (dt1 < thr0) { int c = atomicAdd(&cnt[p0], 1); if (c < 16) lst[p0 * 16 + c] = (unsigned short)(j0 + jl + 1); }
                    if (dt2 < thr1) { int c = atomicAdd(&cnt[p1], 1); if (c < 16) lst[p1 * 16 + c] = (unsigned short)(j0 + jl); }
                    if (dt3 < thr1) { int c = atomicAdd(&cnt[p1], 1); if (c < 16) lst[p1 * 16 + c] = (unsigned short)(j0 + jl + 1); }
                }
            }
        }
        if (round == 0) {
            // reduce screened min across the 4 lanes sharing each point row
            #pragma unroll
            for (int off = 1; off < 4; off <<= 1) {
                run0 = fminf(run0, __shfl_xor_sync(0xFFFFFFFFu, run0, off));
                run1 = fminf(run1, __shfl_xor_sync(0xFFFFFFFFu, run1, off));
            }
            thr0 = run0 + MARGIN;
            thr1 = run1 + MARGIN;
        }
    }
    __syncthreads();

    // ---- exact phase: batched re-evaluation of candidates ----
    for (int idx = tid; idx < 128 * 16; idx += 256) {
        int p = idx >> 4, s = idx & 15;
        int c = cnt[p]; if (c > 16) c = 16;
        if (s < c)
            exact_eval(p, lst[idx], zs32, emb, g_szz[pbase + p], &bestq[p]);
    }
    // overflow fallback (uniform branch; ~never taken)
    for (int p = 0; p < 128; p++) {
        if (cnt[p] > 16) {
            for (int j = tid; j < NE; j += 256)
                exact_eval(p, j, zs32, emb, g_szz[pbase + p], &bestq[p]);
        }
    }
    __syncthreads();

    // ---- results + fused stats ----
    if (tid < 128) {
        int p  = tid;
        int bj = (int)(unsigned)(bestq[p] & 0xFFFFFFFFull);
        int n  = pbase + p;
        sbj[p] = bj;
        g_idx[n] = bj;
        if (OFF_IDX + n < out_size) out[OFF_IDX + n] = (float)bj;
        atomicAdd(&g_cs[bj], 1);
    }
    __syncthreads();
    {
        int p  = tid >> 1;                 // 2 threads per point
        int k0 = (tid & 1) << 5;           // 32 dims each
        float* sp = g_sum + (size_t)sbj[p] * ED;
        #pragma unroll
        for (int kk = 0; kk < 32; kk++)
            atomicAdd(&sp[k0 + kk], zs32[k0 + kk][p]);
    }
}

// ---------------------------------------------------------------------------
// K3: fused EMA — scalar reductions (n, perplexity), inv_csn, and the full
// coalesced codebook update. 1 block x 1024 threads. Same arithmetic and
// op order as the previous split kernels (bit-identical results).
// ---------------------------------------------------------------------------
__global__ __launch_bounds__(1024) void k_ema(const float* __restrict__ ema_cs,
                                              const float* __restrict__ ema_w,
                                              float* __restrict__ out, int out_size)
{
    __shared__ float red[1024];
    __shared__ float inv[1024];
    int j = threadIdx.x;
    const float DEC = 0.99f;
    const float OMD = (float)(1.0 - 0.99);

    float cs  = (float)g_cs[j];
    float ncs = __fadd_rn(__fmul_rn(DEC, ema_cs[j]), __fmul_rn(OMD, cs));

    red[j] = ncs; __syncthreads();
    for (int s = 512; s > 0; s >>= 1) { if (j < s) red[j] = __fadd_rn(red[j], red[j + s]); __syncthreads(); }
    float n = red[0];
    __syncthreads();

    float p    = cs * (1.0f / 32768.0f);
    float term = __fmul_rn(p, logf(__fadd_rn(p, 1e-10f)));
    red[j] = term; __syncthreads();
    for (int s = 512; s > 0; s >>= 1) { if (j < s) red[j] = __fadd_rn(red[j], red[j + s]); __syncthreads(); }
    if (j == 0 && OFF_PERP < out_size) out[OFF_PERP] = expf(-red[0]);

    float denom = __fadd_rn(n, (float)(1024 * 1e-5));
    float csn   = __fmul_rn(__fdiv_rn(__fadd_rn(ncs, 1e-5f), denom), n);
    inv[j] = __fdiv_rn(1.0f, csn);
    __syncthreads();

    // coalesced codebook update: thread j handles elements i*1024 + j
    #pragma unroll 4
    for (int i = 0; i < 64; i++) {
        int m = i * 1024 + j;
        float nw = __fadd_rn(__fmul_rn(DEC, ema_w[m]), __fmul_rn(OMD, g_sum[m]));
        g_new_emb[m] = __fmul_rn(nw, inv[m >> 6]);
    }
}

// ---------------------------------------------------------------------------
// K4: z_q_st = z + (z_q - z), loss sum; LAST block writes the loss scalar.
// ---------------------------------------------------------------------------
__global__ void k_zq(const float* __restrict__ z, float* __restrict__ out, int out_size)
{
    __shared__ float red[256];
    int m = blockIdx.x * 256 + threadIdx.x;
    float sq = 0.f;
    if (m < ZELEMS && OFF_ZQ + m < out_size) {
        int b = m >> 16; int rem = m & 65535;
        int c = rem >> 10; int hw = rem & 1023;
        int n = (b << 10) | hw;
        float zv = z[m];
        float e  = g_new_emb[(size_t)g_idx[n] * ED + c];
        float diff = __fsub_rn(e, zv);
        out[OFF_ZQ + m] = __fadd_rn(zv, diff);
        sq = __fmul_rn(diff, diff);
    }
    red[threadIdx.x] = sq; __syncthreads();
    for (int s = 128; s > 0; s >>= 1) { if (threadIdx.x < s) red[threadIdx.x] += red[threadIdx.x + s]; __syncthreads(); }
    if (threadIdx.x == 0) {
        atomicAdd(&g_loss_sum, red[0]);
        __threadfence();
        unsigned t = atomicAdd(&g_ticket, 1u);
        if (t == 8191u) {               // last block: all adds visible
            if (OFF_LOSS < out_size)
                out[OFF_LOSS] = __fmul_rn(0.25f, __fdiv_rn(g_loss_sum, 2097152.0f));
            g_ticket = 0u;              // reset for next graph replay
        }
    }
}

// ---------------------------------------------------------------------------
// K5: one-hot min_encodings (float4 bulk; row base ≡2 mod 4 elements)
// ---------------------------------------------------------------------------
__global__ void k_menc(float* __restrict__ out, int out_size)
{
    int n = blockIdx.x;
    int j = g_idx[n];
    size_t base = (size_t)OFF_MENC + (size_t)n * NE;
    if (base + NE > (size_t)out_size) return;
    float* row = out + base;
    int t = threadIdx.x;            // 128 threads

    if (t == 0) {
        *(float2*)row          = make_float2(j == 0 ? 1.f : 0.f, j == 1 ? 1.f : 0.f);
        *(float2*)(row + 1022) = make_float2(j == 1022 ? 1.f : 0.f, j == 1023 ? 1.f : 0.f);
    }
    #pragma unroll
    for (int f = t; f < 255; f += 128) {
        int e0 = 2 + (f << 2);
        float4 v = make_float4(0.f, 0.f, 0.f, 0.f);
        int d = j - e0;
        if (d >= 0 && d < 4) ((float*)&v)[d] = 1.0f;
        *(float4*)(row + e0) = v;
    }
}

// ---------------------------------------------------------------------------
extern "C" void kernel_launch(void* const* d_in, const int* in_sizes, int n_in,
                              void* d_out, int out_size)
{
    const float* z = 0; const float* emb = 0; const float* ecs = 0; const float* ew = 0;
    for (int i = 0; i < n_in; i++) {
        if (in_sizes[i] == ZELEMS)      z   = (const float*)d_in[i];
        else if (in_sizes[i] == NE)     ecs = (const float*)d_in[i];
        else if (in_sizes[i] == NE * ED) { if (!emb) emb = (const float*)d_in[i]; else ew = (const float*)d_in[i]; }
    }
    if (!z || !emb || !ecs || !ew) {
        z = (const float*)d_in[0]; emb = (const float*)d_in[1];
        ecs = (const float*)d_in[2]; ew = (const float*)d_in[3];
    }
    float* out = (float*)d_out;

    static int smem_set = 0;
    if (!smem_set) {
        cudaFuncSetAttribute(k_argmin_mma, cudaFuncAttributeMaxDynamicSharedMemorySize, SM_TOT);
        smem_set = 1;
    }

    k_prep       <<<128, 256>>>(z, emb);
    k_argmin_mma <<<256, 256, SM_TOT>>>(z, emb, out, out_size);
    k_ema        <<<1, 1024>>>(ecs, ew, out, out_size);
    k_zq         <<<8192, 256>>>(z, out, out_size);
    k_menc       <<<NPTS, 128>>>(out, out_size);
}

// round 15
// speedup vs baseline: 1.7762x; 1.7762x over previous
#include <cuda_runtime.h>
#include <cuda_bf16.h>
#include <math.h>
#include <float.h>
#include <cstdint>

#define NPTS   32768
#define NE     1024
#define ED     64
#define ZELEMS 2097152

// Output layout: [loss(1), z_q_st(2097152), perplexity(1), min_encodings(33554432), idx(32768)]
#define OFF_LOSS 0
#define OFF_ZQ   1
#define OFF_PERP 2097153
#define OFF_MENC 2097154
#define OFF_IDX  35651586

__device__ float    g_see[NE];
__device__ float    g_szz[NPTS];
__device__ int      g_idx[NPTS];
__device__ int      g_cs[NE];
__device__ float    g_sum[NE * ED];
__device__ float    g_new_emb[NE * ED];
__device__ float    g_inv_csn[NE];
__device__ float    g_loss_sum;

__device__ __forceinline__ uint32_t smem_u32(const void* p) {
    uint32_t a;
    asm("{ .reg .u64 t; cvta.to.shared.u64 t, %1; cvt.u32.u64 %0, t; }" : "=r"(a) : "l"(p));
    return a;
}

// ---------------------------------------------------------------------------
// K1: per-code ||e||^2, per-point ||z||^2, zero accumulators
// ---------------------------------------------------------------------------
__global__ void k_prep(const float* __restrict__ z, const float* __restrict__ emb)
{
    int t = blockIdx.x * 256 + threadIdx.x;   // 32768 threads
    if (t < NE) {
        const float* e = emb + (size_t)t * ED;
        float s = 0.f;
        #pragma unroll
        for (int c = 0; c < ED; c++) { float v = e[c]; s = __fadd_rn(s, __fmul_rn(v, v)); }
        g_see[t] = s;
        g_cs[t]  = 0;
    }
    if (t == 0) g_loss_sum = 0.f;
    if (t < NPTS) {
        int b = t >> 10, hw = t & 1023;
        const float* zp = z + (size_t)b * 65536 + hw;
        float s = 0.f;
        #pragma unroll
        for (int c = 0; c < ED; c++) { float v = zp[(size_t)c << 10]; s = __fadd_rn(s, __fmul_rn(v, v)); }
        g_szz[t] = s;
    }
    g_sum[t]          = 0.f;
    g_sum[t + 32768]  = 0.f;
}

// ---------------------------------------------------------------------------
// K2: two-round bf16 mma.sync screen + batched exact fp32 rescreen + fused
// cluster stats. CTA: 256 thr / 8 warps / 128 points.  (R7, 143.8us proven.)
//
// Round 1: HMMA GEMM over all 1024 codes; epilogue = running min of
//   dt_j = see_j - 2*(z_bf16 . e_bf16)  (4 fminf per n-tile, nothing else).
// Round 2: identical deterministic GEMM; push j with dt_j < min + MARGIN
//   into a per-point smem list (expected 1-3 entries; cap 16 + full-scan
//   fallback on overflow).
// Exact phase: candidates re-evaluated with the EXACT fp32 expression of
//   rounds 1-3 (same fmaf chain, k ascending); u64 (d_bits<<32|j) atomicMin
//   = exact first-index tie-break -> argmin bit-identical to the FFMA kernel.
//   Screen error bound ~1.3e-4 << MARGIN 2e-3 guarantees containment.
//
// Dyn smem: zA bf16 sw 16K | ES bf16 sw 16K | zs32 32K | see 512B |
//           lst u16 4K | cnt 512B | best 1K  = 71680 B -> 2 CTA/SM
// ---------------------------------------------------------------------------
#define SM_ZA    0
#define SM_ES    16384
#define SM_Z32   32768
#define SM_SEE   65536
#define SM_LST   66048
#define SM_CNT   70144
#define SM_BEST  70656
#define SM_TOT   71680

// XOR-swizzled byte offset for [row][k] bf16 tiles, 128B rows, 16B granules
#define SWB(row, kcol) ((uint32_t)(row) * 128u + (uint32_t)(((((kcol) >> 3) ^ ((row) & 7)) << 4) | (((kcol) & 7) << 1)))

__device__ __forceinline__ void exact_eval(int p, int j, const float (*zs32)[128],
                                           const float* __restrict__ emb, float szz,
                                           unsigned long long* bestp)
{
    const float4* ep = (const float4*)(emb + (size_t)j * ED);
    float acc = 0.f;
    #pragma unroll
    for (int k4 = 0; k4 < 16; k4++) {
        float4 e4 = __ldg(ep + k4);
        acc = fmaf(zs32[k4 * 4 + 0][p], e4.x, acc);
        acc = fmaf(zs32[k4 * 4 + 1][p], e4.y, acc);
        acc = fmaf(zs32[k4 * 4 + 2][p], e4.z, acc);
        acc = fmaf(zs32[k4 * 4 + 3][p], e4.w, acc);
    }
    float d = __fsub_rn(__fadd_rn(szz, g_see[j]), __fmul_rn(2.0f, acc));
    unsigned long long key = ((unsigned long long)__float_as_uint(d) << 32) | (unsigned)j;
    atomicMin(bestp, key);
}

__global__ __launch_bounds__(256, 2) void k_argmin_mma(const float* __restrict__ z,
                                                       const float* __restrict__ emb,
                                                       float* __restrict__ out, int out_size)
{
    extern __shared__ char smem[];
    __shared__ int sbj[128];
    const uint32_t sb = smem_u32(smem);
    const int tid  = threadIdx.x;
    const int warp = tid >> 5;
    const int lane = tid & 31;
    const int g    = lane >> 2;       // C-fragment row group 0..7
    const int tig  = lane & 3;        // thread-in-group (column pair)
    const int pbase = blockIdx.x * 128;

    float (*zs32)[128]        = (float (*)[128])(smem + SM_Z32);
    float* see_s              = (float*)(smem + SM_SEE);
    unsigned short* lst       = (unsigned short*)(smem + SM_LST);
    int* cnt                  = (int*)(smem + SM_CNT);
    unsigned long long* bestq = (unsigned long long*)(smem + SM_BEST);

    // ---- load z tile: fp32 [k][p] + bf16 swizzled [p][k]; init cnt/best ----
    for (int i = tid; i < 64 * 128; i += 256) {
        int p = i & 127, k = i >> 7;
        int pn = pbase + p;
        int b = pn >> 10, hw = pn & 1023;
        float v = z[(size_t)b * 65536 + (size_t)k * 1024 + hw];
        zs32[k][p] = v;
        *(__nv_bfloat16*)(smem + SM_ZA + SWB(p, k)) = __float2bfloat16(v);
    }
    if (tid < 128) { cnt[tid] = 0; bestq[tid] = 0xFFFFFFFFFFFFFFFFull; }
    __syncthreads();

    // ---- preload A fragments: warp's 16 points x K=64 (4 k-steps) ----
    uint32_t afr[4][4];
    {
        int m = lane >> 3, r = lane & 7;
        int row = warp * 16 + (m & 1) * 8 + r;
        #pragma unroll
        for (int ks = 0; ks < 4; ks++) {
            int kc = (ks * 2 + (m >> 1)) * 8;
            uint32_t addr = sb + SM_ZA + SWB(row, kc);
            asm volatile("ldmatrix.sync.aligned.m8n8.x4.shared.b16 {%0,%1,%2,%3}, [%4];"
                : "=r"(afr[ks][0]), "=r"(afr[ks][1]), "=r"(afr[ks][2]), "=r"(afr[ks][3])
                : "r"(addr));
        }
    }

    const int p0 = warp * 16 + g;
    const int p1 = p0 + 8;
    const float MARGIN = 2e-3f;
    const int blane = lane & 15;      // ldmatrix.x2 address lanes
    const int bm = blane >> 3, br = blane & 7;

    float run0 = FLT_MAX, run1 = FLT_MAX;
    float thr0 = 0.f, thr1 = 0.f;

    for (int round = 0; round < 2; round++) {
        for (int chunk = 0; chunk < 8; chunk++) {
            const int j0 = chunk * 128;
            __syncthreads();
            // fill 128-code bf16 chunk (swizzled) + see
            for (int i = tid; i < 128 * 16; i += 256) {
                int r  = i >> 4;
                int k4 = (i & 15) << 2;
                float4 v = *(const float4*)(emb + (size_t)(j0 + r) * ED + k4);
                __nv_bfloat16 b4[4] = { __float2bfloat16(v.x), __float2bfloat16(v.y),
                                        __float2bfloat16(v.z), __float2bfloat16(v.w) };
                *(uint2*)(smem + SM_ES + SWB(r, k4)) = *(uint2*)b4;
            }
            if (tid < 128) see_s[tid] = g_see[j0 + tid];
            __syncthreads();

            #pragma unroll 2
            for (int nt = 0; nt < 16; nt++) {
                float acc0 = 0.f, acc1 = 0.f, acc2 = 0.f, acc3 = 0.f;
                #pragma unroll
                for (int ks = 0; ks < 4; ks++) {
                    int row = nt * 8 + br;
                    int kc  = (ks * 2 + bm) * 8;
                    uint32_t addr = sb + SM_ES + SWB(row, kc);
                    uint32_t b0, b1;
                    asm volatile("ldmatrix.sync.aligned.m8n8.x2.shared.b16 {%0,%1}, [%2];"
                        : "=r"(b0), "=r"(b1) : "r"(addr));
                    asm volatile("mma.sync.aligned.m16n8k16.row.col.f32.bf16.bf16.f32 "
                        "{%0,%1,%2,%3}, {%4,%5,%6,%7}, {%8,%9}, {%0,%1,%2,%3};"
                        : "+f"(acc0), "+f"(acc1), "+f"(acc2), "+f"(acc3)
                        : "r"(afr[ks][0]), "r"(afr[ks][1]), "r"(afr[ks][2]), "r"(afr[ks][3]),
                          "r"(b0), "r"(b1));
                }
                int jl  = nt * 8 + tig * 2;
                float seA = see_s[jl], seB = see_s[jl + 1];
                float dt0 = fmaf(acc0, -2.0f, seA);
                float dt1 = fmaf(acc1, -2.0f, seB);
                float dt2 = fmaf(acc2, -2.0f, seA);
                float dt3 = fmaf(acc3, -2.0f, seB);
                if (round == 0) {
                    run0 = fminf(run0, fminf(dt0, dt1));
                    run1 = fminf(run1, fminf(dt2, dt3));
                } else {
                    // push rare candidates (expected ~1-3 per point TOTAL)
                    if (dt0 < thr0) { int c = atomicAdd(&cnt[p0], 1); if (c < 16) lst[p0 * 16 + c] = (unsigned short)(j0 + jl); }
                    if (dt1 < thr0) { int c = atomicAdd(&cnt[p0], 1); if (c < 16) lst[p0 * 16 + c] = (unsigned short)(j0 + jl + 1); }
                    if (dt2 < thr1) { int c = atomicAdd(&cnt[p1], 1); if (c < 16) lst[p1 * 16 + c] = (unsigned short)(j0 + jl); }
                    if (dt3 < thr1) { int c = atomicAdd(&cnt[p1], 1); if (c < 16) lst[p1 * 16 + c] = (unsigned short)(j0 + jl + 1); }
                }
            }
        }
        if (round == 0) {
            // reduce screened min across the 4 lanes sharing each point row
            #pragma unroll
            for (int off = 1; off < 4; off <<= 1) {
                run0 = fminf(run0, __shfl_xor_sync(0xFFFFFFFFu, run0, off));
                run1 = fminf(run1, __shfl_xor_sync(0xFFFFFFFFu, run1, off));
            }
            thr0 = run0 + MARGIN;
            thr1 = run1 + MARGIN;
        }
    }
    __syncthreads();

    // ---- exact phase: batched re-evaluation of candidates ----
    for (int idx = tid; idx < 128 * 16; idx += 256) {
        int p = idx >> 4, s = idx & 15;
        int c = cnt[p]; if (c > 16) c = 16;
        if (s < c)
            exact_eval(p, lst[idx], zs32, emb, g_szz[pbase + p], &bestq[p]);
    }
    // overflow fallback (uniform branch; ~never taken)
    for (int p = 0; p < 128; p++) {
        if (cnt[p] > 16) {
            for (int j = tid; j < NE; j += 256)
                exact_eval(p, j, zs32, emb, g_szz[pbase + p], &bestq[p]);
        }
    }
    __syncthreads();

    // ---- results + fused stats ----
    if (tid < 128) {
        int p  = tid;
        int bj = (int)(unsigned)(bestq[p] & 0xFFFFFFFFull);
        int n  = pbase + p;
        sbj[p] = bj;
        g_idx[n] = bj;
        if (OFF_IDX + n < out_size) out[OFF_IDX + n] = (float)bj;
        atomicAdd(&g_cs[bj], 1);
    }
    __syncthreads();
    {
        int p  = tid >> 1;                 // 2 threads per point
        int k0 = (tid & 1) << 5;           // 32 dims each
        float* sp = g_sum + (size_t)sbj[p] * ED;
        #pragma unroll
        for (int kk = 0; kk < 32; kk++)
            atomicAdd(&sp[k0 + kk], zs32[k0 + kk][p]);
    }
}

// ---------------------------------------------------------------------------
// K3a: scalar reductions (n, perplexity) + one reciprocal per code
// ---------------------------------------------------------------------------
__global__ __launch_bounds__(1024) void k_ema_reduce(const float* __restrict__ ema_cs,
                                                     float* __restrict__ out, int out_size)
{
    __shared__ float red[1024];
    int j = threadIdx.x;
    const float DEC = 0.99f;
    const float OMD = (float)(1.0 - 0.99);

    float cs  = (float)g_cs[j];
    float ncs = __fadd_rn(__fmul_rn(DEC, ema_cs[j]), __fmul_rn(OMD, cs));

    red[j] = ncs; __syncthreads();
    for (int s = 512; s > 0; s >>= 1) { if (j < s) red[j] = __fadd_rn(red[j], red[j + s]); __syncthreads(); }
    float n = red[0];
    __syncthreads();

    float p    = cs * (1.0f / 32768.0f);
    float term = __fmul_rn(p, logf(__fadd_rn(p, 1e-10f)));
    red[j] = term; __syncthreads();
    for (int s = 512; s > 0; s >>= 1) { if (j < s) red[j] = __fadd_rn(red[j], red[j + s]); __syncthreads(); }
    if (j == 0 && OFF_PERP < out_size) out[OFF_PERP] = expf(-red[0]);

    float denom = __fadd_rn(n, (float)(1024 * 1e-5));
    float csn   = __fmul_rn(__fdiv_rn(__fadd_rn(ncs, 1e-5f), denom), n);
    g_inv_csn[j] = __fdiv_rn(1.0f, csn);
}

// ---------------------------------------------------------------------------
// K3b: codebook update, fully parallel over 1024x64 elements
// ---------------------------------------------------------------------------
__global__ void k_ema_update(const float* __restrict__ ema_w)
{
    int m = blockIdx.x * 256 + threadIdx.x;   // 65536 threads
    const float DEC = 0.99f;
    const float OMD = (float)(1.0 - 0.99);
    int j = m >> 6;
    float nw = __fadd_rn(__fmul_rn(DEC, ema_w[m]), __fmul_rn(OMD, g_sum[m]));
    g_new_emb[m] = __fmul_rn(nw, g_inv_csn[j]);
}

// ---------------------------------------------------------------------------
// K4: z_q_st = z + (z_q - z), loss sum — vectorized LOADS (float4 z at
// 16B-aligned m, int4 idx at 16B-aligned n), SCALAR stores (out+1+m is only
// 4B-aligned; STG.128 would trap). Per-element arithmetic unchanged.
// ---------------------------------------------------------------------------
__global__ void k_zq(const float* __restrict__ z, float* __restrict__ out, int out_size)
{
    __shared__ float red[256];
    int q = blockIdx.x * 256 + threadIdx.x;   // quad index, 524288 total
    int m = q << 2;
    float sq = 0.f;
    if (m < ZELEMS && OFF_ZQ + m + 3 < out_size) {
        int b = m >> 16; int rem = m & 65535;
        int c = rem >> 10; int hw = rem & 1023;
        int n = (b << 10) | hw;                 // 4-aligned
        float4 zv = *(const float4*)(z + m);
        int4  jj  = *(const int4*)(g_idx + n);
        float e0 = g_new_emb[(size_t)jj.x * ED + c];
        float e1 = g_new_emb[(size_t)jj.y * ED + c];
        float e2 = g_new_emb[(size_t)jj.z * ED + c];
        float e3 = g_new_emb[(size_t)jj.w * ED + c];
        float d0 = __fsub_rn(e0, zv.x);
        float d1 = __fsub_rn(e1, zv.y);
        float d2 = __fsub_rn(e2, zv.z);
        float d3 = __fsub_rn(e3, zv.w);
        float* o = out + OFF_ZQ + m;            // 4B-aligned only: scalar STG
        o[0] = __fadd_rn(zv.x, d0);
        o[1] = __fadd_rn(zv.y, d1);
        o[2] = __fadd_rn(zv.z, d2);
        o[3] = __fadd_rn(zv.w, d3);
        sq = __fmul_rn(d0, d0);
        sq = fmaf(d1, d1, sq);
        sq = fmaf(d2, d2, sq);
        sq = fmaf(d3, d3, sq);
    }
    red[threadIdx.x] = sq; __syncthreads();
    for (int s = 128; s > 0; s >>= 1) { if (threadIdx.x < s) red[threadIdx.x] += red[threadIdx.x + s]; __syncthreads(); }
    if (threadIdx.x == 0) atomicAdd(&g_loss_sum, red[0]);
}

// ---------------------------------------------------------------------------
// K5: one-hot min_encodings (float4 bulk; row base ≡2 mod 4 elements),
// loss folded into block 0.
// ---------------------------------------------------------------------------
__global__ void k_menc(float* __restrict__ out, int out_size)
{
    int n = blockIdx.x;
    int j = g_idx[n];
    size_t base = (size_t)OFF_MENC + (size_t)n * NE;
    if (base + NE > (size_t)out_size) return;
    float* row = out + base;
    int t = threadIdx.x;            // 128 threads

    if (t == 0) {
        *(float2*)row          = make_float2(j == 0 ? 1.f : 0.f, j == 1 ? 1.f : 0.f);
        *(float2*)(row + 1022) = make_float2(j == 1022 ? 1.f : 0.f, j == 1023 ? 1.f : 0.f);
        if (n == 0 && OFF_LOSS < out_size)
            out[OFF_LOSS] = __fmul_rn(0.25f, __fdiv_rn(g_loss_sum, 2097152.0f));
    }
    #pragma unroll
    for (int f = t; f < 255; f += 128) {
        int e0 = 2 + (f << 2);
        float4 v = make_float4(0.f, 0.f, 0.f, 0.f);
        int d = j - e0;
        if (d >= 0 && d < 4) ((float*)&v)[d] = 1.0f;
        *(float4*)(row + e0) = v;
    }
}

// ---------------------------------------------------------------------------
extern "C" void kernel_launch(void* const* d_in, const int* in_sizes, int n_in,
                              void* d_out, int out_size)
{
    const float* z = 0; const float* emb = 0; const float* ecs = 0; const float* ew = 0;
    for (int i = 0; i < n_in; i++) {
        if (in_sizes[i] == ZELEMS)      z   = (const float*)d_in[i];
        else if (in_sizes[i] == NE)     ecs = (const float*)d_in[i];
        else if (in_sizes[i] == NE * ED) { if (!emb) emb = (const float*)d_in[i]; else ew = (const float*)d_in[i]; }
    }
    if (!z || !emb || !ecs || !ew) {
        z = (const float*)d_in[0]; emb = (const float*)d_in[1];
        ecs = (const float*)d_in[2]; ew = (const float*)d_in[3];
    }
    float* out = (float*)d_out;

    static int smem_set = 0;
    if (!smem_set) {
        cudaFuncSetAttribute(k_argmin_mma, cudaFuncAttributeMaxDynamicSharedMemorySize, SM_TOT);
        smem_set = 1;
    }

    k_prep       <<<128, 256>>>(z, emb);
    k_argmin_mma <<<256, 256, SM_TOT>>>(z, emb, out, out_size);
    k_ema_reduce <<<1, 1024>>>(ecs, out, out_size);
    k_ema_update <<<256, 256>>>(ew);
    k_zq         <<<2048, 256>>>(z, out, out_size);
    k_menc       <<<NPTS, 128>>>(out, out_size);
}